// round 2
// baseline (speedup 1.0000x reference)
#include <cuda_runtime.h>
#include <math.h>

// SE(3) exp + point transform.
// X_v: [B,T,N,3] f32, dofs: [B,T,6] f32, out: [B,T,N,3] f32.
// B=64, T=28, N=4096 (but written generically for N % 1024 == 0 per-slice tiling
// with tail handling).

#define THREADS 256
#define PTS_PER_THREAD 4   // 4 points = 12 floats = 3 float4

__global__ void __launch_bounds__(THREADS)
se3_transform_kernel(const float* __restrict__ X,
                     const float* __restrict__ dofs,
                     float* __restrict__ out,
                     int N)
{
    __shared__ float sRT[12];   // R row-major [9], then t [3]

    const int bt = blockIdx.y;

    if (threadIdx.x == 0) {
        const float* d = dofs + bt * 6;
        const float tx = d[0], ty = d[1], tz = d[2];
        const float wx = d[3], wy = d[4], wz = d[5];

        const float nrm   = wx*wx + wy*wy + wz*wz;
        const float th2c  = fmaxf(nrm, 1.0e-4f);   // clip BEFORE sqrt (matches ref)
        const float theta = sqrtf(th2c);
        float st, ct;
        sincosf(theta, &st, &ct);
        const float f1 = st / theta;
        const float f2 = (1.0f - ct) / (theta * theta);
        const float f3 = (theta - st) / (theta * theta * theta);

        // H = hat(w); H2 = H@H = w w^T - (w.w) I   (raw nrm, matches ref H@H)
        // R = I + f1*H + f2*H2
        const float h2xx = wx*wx - nrm, h2yy = wy*wy - nrm, h2zz = wz*wz - nrm;
        const float h2xy = wx*wy, h2xz = wx*wz, h2yz = wy*wz;

        const float r00 = 1.0f + f2*h2xx;
        const float r01 = -f1*wz + f2*h2xy;
        const float r02 =  f1*wy + f2*h2xz;
        const float r10 =  f1*wz + f2*h2xy;
        const float r11 = 1.0f + f2*h2yy;
        const float r12 = -f1*wx + f2*h2yz;
        const float r20 = -f1*wy + f2*h2xz;
        const float r21 =  f1*wx + f2*h2yz;
        const float r22 = 1.0f + f2*h2zz;

        // V = I + f2*H + f3*H2 ; t = V @ t_log
        const float v00 = 1.0f + f3*h2xx;
        const float v01 = -f2*wz + f3*h2xy;
        const float v02 =  f2*wy + f3*h2xz;
        const float v10 =  f2*wz + f3*h2xy;
        const float v11 = 1.0f + f3*h2yy;
        const float v12 = -f2*wx + f3*h2yz;
        const float v20 = -f2*wy + f3*h2xz;
        const float v21 =  f2*wx + f3*h2yz;
        const float v22 = 1.0f + f3*h2zz;

        sRT[0] = r00; sRT[1] = r01; sRT[2] = r02;
        sRT[3] = r10; sRT[4] = r11; sRT[5] = r12;
        sRT[6] = r20; sRT[7] = r21; sRT[8] = r22;
        sRT[9]  = v00*tx + v01*ty + v02*tz;
        sRT[10] = v10*tx + v11*ty + v12*tz;
        sRT[11] = v20*tx + v21*ty + v22*tz;
    }
    __syncthreads();

    const float r00 = sRT[0], r01 = sRT[1], r02 = sRT[2];
    const float r10 = sRT[3], r11 = sRT[4], r12 = sRT[5];
    const float r20 = sRT[6], r21 = sRT[7], r22 = sRT[8];
    const float t0  = sRT[9], t1  = sRT[10], t2 = sRT[11];

    // Each thread: 4 points = 12 floats = 3 float4 (all 16B aligned since
    // slice base (N*3 floats) and per-thread offset (12 floats) are multiples of 4).
    const int ptBase = (blockIdx.x * THREADS + threadIdx.x) * PTS_PER_THREAD;
    if (ptBase >= N) return;

    const size_t base = (size_t)bt * (size_t)N * 3 + (size_t)ptBase * 3;
    const float4* __restrict__ src = reinterpret_cast<const float4*>(X + base);
    float4* __restrict__ dst = reinterpret_cast<float4*>(out + base);

    const float4 a = src[0];   // x0 y0 z0 x1
    const float4 b = src[1];   // y1 z1 x2 y2
    const float4 c = src[2];   // z2 x3 y3 z3

    // point 0
    const float o0x = fmaf(r00, a.x, fmaf(r01, a.y, fmaf(r02, a.z, t0)));
    const float o0y = fmaf(r10, a.x, fmaf(r11, a.y, fmaf(r12, a.z, t1)));
    const float o0z = fmaf(r20, a.x, fmaf(r21, a.y, fmaf(r22, a.z, t2)));
    // point 1: (a.w, b.x, b.y)
    const float o1x = fmaf(r00, a.w, fmaf(r01, b.x, fmaf(r02, b.y, t0)));
    const float o1y = fmaf(r10, a.w, fmaf(r11, b.x, fmaf(r12, b.y, t1)));
    const float o1z = fmaf(r20, a.w, fmaf(r21, b.x, fmaf(r22, b.y, t2)));
    // point 2: (b.z, b.w, c.x)
    const float o2x = fmaf(r00, b.z, fmaf(r01, b.w, fmaf(r02, c.x, t0)));
    const float o2y = fmaf(r10, b.z, fmaf(r11, b.w, fmaf(r12, c.x, t1)));
    const float o2z = fmaf(r20, b.z, fmaf(r21, b.w, fmaf(r22, c.x, t2)));
    // point 3: (c.y, c.z, c.w)
    const float o3x = fmaf(r00, c.y, fmaf(r01, c.z, fmaf(r02, c.w, t0)));
    const float o3y = fmaf(r10, c.y, fmaf(r11, c.z, fmaf(r12, c.w, t1)));
    const float o3z = fmaf(r20, c.y, fmaf(r21, c.z, fmaf(r22, c.w, t2)));

    dst[0] = make_float4(o0x, o0y, o0z, o1x);
    dst[1] = make_float4(o1y, o1z, o2x, o2y);
    dst[2] = make_float4(o2z, o3x, o3y, o3z);
}

extern "C" void kernel_launch(void* const* d_in, const int* in_sizes, int n_in,
                              void* d_out, int out_size)
{
    const float* X    = (const float*)d_in[0];   // [B,T,N,3]
    const float* dofs = (const float*)d_in[1];   // [B,T,6]

    const int nBT = in_sizes[1] / 6;             // 64*28 = 1792
    const int N   = (in_sizes[0] / nBT) / 3;     // 4096

    const int ptsPerBlock = THREADS * PTS_PER_THREAD;        // 1024
    const int blocksX = (N + ptsPerBlock - 1) / ptsPerBlock; // 4

    dim3 grid(blocksX, nBT);
    se3_transform_kernel<<<grid, THREADS>>>(X, dofs, (float*)d_out, N);
}